// round 14
// baseline (speedup 1.0000x reference)
#include <cuda_runtime.h>
#include <math.h>

#define TSTEPS  2048
#define FDIM    15
#define NGROUPS 8
#define BG      8      // batch rows per group
#define NT      384
#define NCTA    128
#define CK      36     // k-chunk stride (32 data + 4 pad floats)
#define SPH     288    // padded row stride for h state = 8*CK
#define WS      288    // padded row stride for weights = 8*CK
#define RB      148    // red row stride
#define RKC     1188   // red kc stride = 8*RB + 4

typedef unsigned long long u64;

// Double-buffered hidden states (tiny: live in L2)
__device__ float    g_h1[2 * NGROUPS * BG * 256];
__device__ float    g_h2[2 * NGROUPS * BG * 256];
__device__ unsigned g_flags[NCTA];

__global__ void init_kernel() {
    if (threadIdx.x < NCTA) g_flags[threadIdx.x] = 0u;
}

__device__ __forceinline__ float sigmoidf_(float x) {
    return __fdividef(1.0f, 1.0f + __expf(-x));
}

// packed f32x2 fma
__device__ __forceinline__ u64 ffma2(u64 a, u64 b, u64 c) {
    u64 d;
    asm("fma.rn.f32x2 %0, %1, %2, %3;" : "=l"(d) : "l"(a), "l"(b), "l"(c));
    return d;
}

// arrive: block sync, then tid0 fences + publishes epoch to this CTA's flag
__device__ __forceinline__ void bar_arrive(unsigned cta, unsigned e) {
    __syncthreads();
    if (threadIdx.x == 0) {
        __threadfence();
        atomicExch(&g_flags[cta], e);
    }
}
// wait: warp 0 polls all 16 flags of the group (one 64B sector), broadcast via bar
__device__ __forceinline__ void bar_wait(int grp, unsigned e) {
    if (threadIdx.x < 32) {
        int lane = threadIdx.x;
        for (;;) {
            unsigned v = e;
            if (lane < 16) v = ((volatile unsigned*)g_flags)[grp * 16 + lane];
            if (__all_sync(0xffffffffu, v >= e)) break;
        }
        if (lane == 0) __threadfence();
    }
    __syncthreads();
}

__global__ void __launch_bounds__(NT, 1)
gru_kernel(const float* __restrict__ inp, const float* __restrict__ W1,
           const float* __restrict__ U1g, const float* __restrict__ b1,
           const float* __restrict__ W2g, const float* __restrict__ U2g,
           const float* __restrict__ b2, float* __restrict__ out)
{
    extern __shared__ float smem[];
    float* sW    = smem;                  // [144][WS]: 0..47 U1, 48..95 W2, 96..143 U2 (transposed, chunked k)
    float* sh1   = sW    + 144 * WS;      // [8][SPH]  h1[i-1] (chunked k)
    float* sh2   = sh1   +   8 * SPH;     // [8][SPH]  h2[i-2] (chunked k)
    float* sW1t  = sh2   +   8 * SPH;     // [48][16]
    float* sx    = sW1t  +  48 * 16;      // [8][16]
    float* sb    = sx    +   8 * 16;      // [4*48]: b1_in | b1_rec | b2_in | b2_rec
    float* red   = sb    +   4 * 48;      // [8 kc][8 rows * RB]

    const int tid   = threadIdx.x;
    const int cta   = blockIdx.x;
    const int grp   = cta >> 4;
    const int sl    = cta & 15;
    const int brow0 = grp * BG;

    // ---- one-time: load weight slices (transposed, chunked k) into SMEM ----
    for (int idx = tid; idx < 48 * 256; idx += NT) {
        int k = idx / 48, c = idx - k * 48;
        int col = ((c >> 4) << 8) + (sl << 4) + (c & 15);   // gate*256 + slice*16 + u
        int ko  = (k >> 5) * CK + (k & 31);                 // chunked k offset
        sW[c * WS + ko]          = U1g[k * 768 + col];
        sW[(48 + c) * WS + ko]   = W2g[k * 768 + col];
        sW[(96 + c) * WS + ko]   = U2g[k * 768 + col];
    }
    for (int idx = tid; idx < 48 * 15; idx += NT) {
        int f = idx / 48, c = idx - f * 48;
        int col = ((c >> 4) << 8) + (sl << 4) + (c & 15);
        sW1t[c * 16 + f] = W1[f * 768 + col];
    }
    for (int c = tid; c < 48; c += NT) {
        int col = ((c >> 4) << 8) + (sl << 4) + (c & 15);
        sb[c]        = b1[col];        // b1_in
        sb[48 + c]   = b1[768 + col];  // b1_rec
        sb[96 + c]   = b2[col];        // b2_in
        sb[144 + c]  = b2[768 + col];  // b2_rec
    }
    if (tid < 128) {
        int b = tid & 7, u = tid >> 3;
        int scol = (sl << 4) + u;
        for (int buf = 0; buf < 2; buf++) {
            g_h1[(buf * NGROUPS + grp) * BG * 256 + b * 256 + scol] = 0.f;
            g_h2[(buf * NGROUPS + grp) * BG * 256 + b * 256 + scol] = 0.f;
        }
    }

    // GEMM decomposition: tid = cg*16 + kc*2 + rh  (warp = 2 cg x 8 kc x 2 rh)
    const int cg  = tid >> 4;          // 0..23 (cols cg*6..cg*6+5; cg<16 -> h1, else h2)
    const int r16 = tid & 15;
    const int kc  = r16 >> 1;          // 0..7  (k chunk of 32)
    const int rh  = r16 & 1;           // 0..1  (4 rows each)
    const float* hsel = (cg < 16 ? sh1 : sh2) + rh * 4 * SPH + kc * CK;
    const float* wbse = sW + (cg * 6) * WS + kc * CK;

    const int b15 = tid / 15, f15 = tid - b15 * 15;   // input-load map (tid<120)

    // register-resident own state element
    float hp1 = 0.f;   // valid for tid < 128
    float hp2 = 0.f;   // valid for 128 <= tid < 256

    bar_arrive(cta, 1u);
    bar_wait(grp, 1u);

    for (int i = 0; i <= TSTEPS; ++i) {
        // ---- prefetch input row i (independent of barrier) ----
        float xin = 0.f;
        if (i < TSTEPS && tid < 120)
            xin = __ldg(&inp[(size_t)(brow0 + b15) * (TSTEPS * FDIM) + i * FDIM + f15]);

        if (i > 0) bar_wait(grp, (unsigned)(i + 1));

        // ---- phase 1: load shared state (L2-coherent) into chunked layout ----
        {
            const float* gh1 = g_h1 + (((i + 1) & 1) * NGROUPS + grp) * BG * 256;  // h1[i-1]
            const float* gh2 = g_h2 + (((i) & 1)     * NGROUPS + grp) * BG * 256;  // h2[i-2]
            for (int idx = tid; idx < 512; idx += NT) {
                int b = idx >> 6, k4 = idx & 63;
                int so = b * SPH + (k4 >> 3) * CK + ((k4 & 7) << 2);
                float4 v1 = __ldcg(((const float4*)(gh1 + b * 256)) + k4);
                float4 v2 = __ldcg(((const float4*)(gh2 + b * 256)) + k4);
                *(float4*)(sh1 + so) = v1;
                *(float4*)(sh2 + so) = v2;
            }
            if (i < TSTEPS && tid < 120) sx[b15 * 16 + f15] = xin;
        }
        __syncthreads();

        // ---- phase 2: fused register-tiled GEMM (384 threads, 4x6 tile) ----
        {
            u64 acc[4][6];
            #pragma unroll
            for (int j = 0; j < 4; j++)
                #pragma unroll
                for (int jj = 0; jj < 6; jj++) acc[j][jj] = 0ull;

            #pragma unroll
            for (int s = 0; s < 8; s++) {
                ulonglong2 h2v[4];
                #pragma unroll
                for (int j = 0; j < 4; j++)
                    h2v[j] = *(const ulonglong2*)(hsel + j * SPH + s * 4);
                #pragma unroll
                for (int jj = 0; jj < 6; jj++) {
                    ulonglong2 w2 = *(const ulonglong2*)(wbse + jj * WS + s * 4);
                    #pragma unroll
                    for (int j = 0; j < 4; j++) {
                        acc[j][jj] = ffma2(h2v[j].x, w2.x, acc[j][jj]);
                        acc[j][jj] = ffma2(h2v[j].y, w2.y, acc[j][jj]);
                    }
                }
            }
            #pragma unroll
            for (int j = 0; j < 4; j++) {
                int row = rh * 4 + j;
                #pragma unroll
                for (int jj = 0; jj < 6; jj += 2) {
                    float2 p0 = *(float2*)&acc[j][jj];
                    float2 p1 = *(float2*)&acc[j][jj + 1];
                    *(float2*)&red[kc * RKC + row * RB + cg * 6 + jj] =
                        make_float2(p0.x + p0.y, p1.x + p1.y);
                }
            }
        }
        __syncthreads();

        // ---- phase 3: parallel gates with fused k-reduce ----
        if (tid < 128) {
            // layer 1: h1[i]
            if (i < TSTEPS) {
                int b = tid & 7, u = tid >> 3;
                int scol = (sl << 4) + u;
                const float* rrow = red + b * RB;
                float rec[3], xp[3];
                #pragma unroll
                for (int g = 0; g < 3; g++) {
                    int c = g * 16 + u;
                    float s = rrow[c];
                    #pragma unroll
                    for (int k2 = 1; k2 < 8; k2++) s += rrow[k2 * RKC + c];
                    rec[g] = s + sb[48 + c];                 // + b1_rec
                    float a = sb[c];                         // b1_in
                    const float* wr = sW1t + c * 16;
                    const float* xr = sx + b * 16;
                    #pragma unroll
                    for (int f = 0; f < 15; f++) a += xr[f] * wr[f];
                    xp[g] = a;
                }
                float z  = sigmoidf_(xp[0] + rec[0]);
                float r  = sigmoidf_(xp[1] + rec[1]);
                float hh = fmaxf(0.f, xp[2] + r * rec[2]);
                float hn = z * hp1 + (1.f - z) * hh;
                hp1 = hn;
                g_h1[((i & 1) * NGROUPS + grp) * BG * 256 + b * 256 + scol] = hn;
                if (i == TSTEPS - 1) out[64 * 256 + (brow0 + b) * 256 + scol] = hn;  // state1
            }
        } else if (tid < 256) {
            // layer 2: h2[i-1]
            if (i >= 1) {
                int bu = tid - 128;
                int b = bu & 7, u = bu >> 3;
                int scol = (sl << 4) + u;
                int gb = brow0 + b;
                const float* rrow = red + b * RB;
                float xpv[3], rec[3];
                #pragma unroll
                for (int g = 0; g < 3; g++) {
                    int cx = 48 + g * 16 + u;
                    int cr = 96 + g * 16 + u;
                    float sx_ = rrow[cx];
                    float sr_ = rrow[cr];
                    #pragma unroll
                    for (int k2 = 1; k2 < 8; k2++) {
                        sx_ += rrow[k2 * RKC + cx];
                        sr_ += rrow[k2 * RKC + cr];
                    }
                    xpv[g] = sx_ + sb[96 + g * 16 + u];   // + b2_in
                    rec[g] = sr_ + sb[144 + g * 16 + u];  // + b2_rec
                }
                float z  = sigmoidf_(xpv[0] + rec[0]);
                float r  = sigmoidf_(xpv[1] + rec[1]);
                float hh = fmaxf(0.f, xpv[2] + r * rec[2]);
                float hn = z * hp2 + (1.f - z) * hh;
                hp2 = hn;
                g_h2[(((i - 1) & 1) * NGROUPS + grp) * BG * 256 + b * 256 + scol] = hn;
                if (i == TSTEPS) {
                    out[gb * 256 + scol]                = hn;   // x = seq2[:, -1, :]
                    out[2 * 64 * 256 + gb * 256 + scol] = hn;   // state2
                }
            }
        }

        bar_arrive(cta, (unsigned)(i + 2));
    }
}

extern "C" void kernel_launch(void* const* d_in, const int* in_sizes, int n_in,
                              void* d_out, int out_size) {
    const float* inp = (const float*)d_in[0];
    const float* W1  = (const float*)d_in[1];
    const float* U1  = (const float*)d_in[2];
    const float* b1  = (const float*)d_in[3];
    const float* W2  = (const float*)d_in[4];
    const float* U2  = (const float*)d_in[5];
    const float* b2  = (const float*)d_in[6];
    float* out = (float*)d_out;

    size_t smem_bytes = (size_t)(144 * WS + 2 * 8 * SPH +
                                 48 * 16 + 8 * 16 + 4 * 48 +
                                 8 * RKC) * sizeof(float);
    cudaFuncSetAttribute(gru_kernel, cudaFuncAttributeMaxDynamicSharedMemorySize,
                         (int)smem_bytes);
    init_kernel<<<1, 128>>>();
    gru_kernel<<<NCTA, NT, smem_bytes>>>(inp, W1, U1, b1, W2, U2, b2, out);
}

// round 15
// speedup vs baseline: 1.0034x; 1.0034x over previous
#include <cuda_runtime.h>
#include <math.h>

#define TSTEPS  2048
#define FDIM    15
#define NGROUPS 8
#define BG      8      // batch rows per group
#define NT      384
#define NCTA    128
#define SPH     260    // padded row stride for h state (floats), 16B-aligned rows
#define WS      260    // padded row stride for weights (floats), 16B-aligned rows
#define RB      148    // red row stride
#define RKC     1188   // red kc stride = 8*RB + 4

typedef unsigned long long u64;

// Double-buffered hidden states (tiny: live in L2)
__device__ float    g_h1[2 * NGROUPS * BG * 256];
__device__ float    g_h2[2 * NGROUPS * BG * 256];
__device__ unsigned g_flags[NCTA];

__global__ void init_kernel() {
    if (threadIdx.x < NCTA) g_flags[threadIdx.x] = 0u;
}

__device__ __forceinline__ float sigmoidf_(float x) {
    return __fdividef(1.0f, 1.0f + __expf(-x));
}

// packed f32x2 fma
__device__ __forceinline__ u64 ffma2(u64 a, u64 b, u64 c) {
    u64 d;
    asm("fma.rn.f32x2 %0, %1, %2, %3;" : "=l"(d) : "l"(a), "l"(b), "l"(c));
    return d;
}

// arrive: block sync, then tid0 fences + publishes epoch to this CTA's flag
__device__ __forceinline__ void bar_arrive(unsigned cta, unsigned e) {
    __syncthreads();
    if (threadIdx.x == 0) {
        __threadfence();
        atomicExch(&g_flags[cta], e);
    }
}
// wait: warp 0 polls all 16 flags of the group (one 64B sector), broadcast via bar
__device__ __forceinline__ void bar_wait(int grp, unsigned e) {
    if (threadIdx.x < 32) {
        int lane = threadIdx.x;
        for (;;) {
            unsigned v = e;
            if (lane < 16) v = ((volatile unsigned*)g_flags)[grp * 16 + lane];
            if (__all_sync(0xffffffffu, v >= e)) break;
        }
        if (lane == 0) __threadfence();
    }
    __syncthreads();
}

__global__ void __launch_bounds__(NT, 1)
gru_kernel(const float* __restrict__ inp, const float* __restrict__ W1,
           const float* __restrict__ U1g, const float* __restrict__ b1,
           const float* __restrict__ W2g, const float* __restrict__ U2g,
           const float* __restrict__ b2, float* __restrict__ out)
{
    extern __shared__ float smem[];
    float* sW    = smem;                  // [144][WS]: 0..47 U1, 48..95 W2, 96..143 U2 (transposed)
    float* sh1   = sW    + 144 * WS;      // [8][SPH]  h1[i-1]
    float* sh2   = sh1   +   8 * SPH;     // [8][SPH]  h2[i-2]
    float* sW1t  = sh2   +   8 * SPH;     // [48][16]
    float* sx    = sW1t  +  48 * 16;      // [8][16]
    float* sb    = sx    +   8 * 16;      // [4*48]: b1_in | b1_rec | b2_in | b2_rec
    float* red   = sb    +   4 * 48;      // [8 kc][8 rows * RB]

    const int tid   = threadIdx.x;
    const int cta   = blockIdx.x;
    const int grp   = cta >> 4;
    const int sl    = cta & 15;
    const int brow0 = grp * BG;

    // ---- one-time: load weight slices (transposed) into SMEM ----
    for (int idx = tid; idx < 48 * 256; idx += NT) {
        int k = idx / 48, c = idx - k * 48;
        int col = ((c >> 4) << 8) + (sl << 4) + (c & 15);   // gate*256 + slice*16 + u
        sW[c * WS + k]          = U1g[k * 768 + col];
        sW[(48 + c) * WS + k]   = W2g[k * 768 + col];
        sW[(96 + c) * WS + k]   = U2g[k * 768 + col];
    }
    for (int idx = tid; idx < 48 * 15; idx += NT) {
        int f = idx / 48, c = idx - f * 48;
        int col = ((c >> 4) << 8) + (sl << 4) + (c & 15);
        sW1t[c * 16 + f] = W1[f * 768 + col];
    }
    for (int c = tid; c < 48; c += NT) {
        int col = ((c >> 4) << 8) + (sl << 4) + (c & 15);
        sb[c]        = b1[col];        // b1_in
        sb[48 + c]   = b1[768 + col];  // b1_rec
        sb[96 + c]   = b2[col];        // b2_in
        sb[144 + c]  = b2[768 + col];  // b2_rec
    }
    if (tid < 128) {
        int b = tid & 7, u = tid >> 3;
        int scol = (sl << 4) + u;
        for (int buf = 0; buf < 2; buf++) {
            g_h1[(buf * NGROUPS + grp) * BG * 256 + b * 256 + scol] = 0.f;
            g_h2[(buf * NGROUPS + grp) * BG * 256 + b * 256 + scol] = 0.f;
        }
    }
    __syncthreads();

    // GEMM decomposition (all 384 threads): kc (k-chunk of 32) x cg (6 cols) x rh (4 rows)
    const int kc  = tid / 48;          // 0..7
    const int r48 = tid - kc * 48;
    const int cg  = r48 >> 1;          // 0..23 (cols cg*6..cg*6+5; cg<16 -> h1, else h2)
    const int rh  = r48 & 1;           // 0..1
    const float* hsel = (cg < 16 ? sh1 : sh2) + rh * 4 * SPH + kc * 32;
    const float* wbse = sW + (cg * 6) * WS + kc * 32;

    // ---- register-cache weight columns 0..3 of this thread's 6 columns ----
    ulonglong2 wc[4][8];
    #pragma unroll
    for (int jj = 0; jj < 4; jj++)
        #pragma unroll
        for (int s = 0; s < 8; s++)
            wc[jj][s] = *(const ulonglong2*)(wbse + jj * WS + s * 4);

    const int b15 = tid / 15, f15 = tid - b15 * 15;   // input-load map (tid<120)

    // register-resident own state element
    float hp1 = 0.f;   // valid for tid < 128
    float hp2 = 0.f;   // valid for 128 <= tid < 256

    bar_arrive(cta, 1u);
    bar_wait(grp, 1u);

    for (int i = 0; i <= TSTEPS; ++i) {
        // ---- prefetch input row i (independent of barrier) ----
        float xin = 0.f;
        if (i < TSTEPS && tid < 120)
            xin = __ldg(&inp[(size_t)(brow0 + b15) * (TSTEPS * FDIM) + i * FDIM + f15]);

        if (i > 0) bar_wait(grp, (unsigned)(i + 1));

        // ---- phase 1: load shared state (L2-coherent) ----
        {
            const float* gh1 = g_h1 + (((i + 1) & 1) * NGROUPS + grp) * BG * 256;  // h1[i-1]
            const float* gh2 = g_h2 + (((i) & 1)     * NGROUPS + grp) * BG * 256;  // h2[i-2]
            for (int idx = tid; idx < 512; idx += NT) {
                int b = idx >> 6, k4 = idx & 63;
                float4 v1 = __ldcg(((const float4*)(gh1 + b * 256)) + k4);
                float4 v2 = __ldcg(((const float4*)(gh2 + b * 256)) + k4);
                *(float4*)(sh1 + b * SPH + (k4 << 2)) = v1;
                *(float4*)(sh2 + b * SPH + (k4 << 2)) = v2;
            }
            if (i < TSTEPS && tid < 120) sx[b15 * 16 + f15] = xin;
        }
        __syncthreads();

        // ---- phase 2: fused register-tiled GEMM (4x6 tile, 4 w-cols cached in regs) ----
        {
            u64 acc[4][6];
            #pragma unroll
            for (int j = 0; j < 4; j++)
                #pragma unroll
                for (int jj = 0; jj < 6; jj++) acc[j][jj] = 0ull;

            #pragma unroll
            for (int s = 0; s < 8; s++) {
                ulonglong2 h2v[4];
                #pragma unroll
                for (int j = 0; j < 4; j++)
                    h2v[j] = *(const ulonglong2*)(hsel + j * SPH + s * 4);
                // cached columns 0..3
                #pragma unroll
                for (int jj = 0; jj < 4; jj++) {
                    ulonglong2 w2 = wc[jj][s];
                    #pragma unroll
                    for (int j = 0; j < 4; j++) {
                        acc[j][jj] = ffma2(h2v[j].x, w2.x, acc[j][jj]);
                        acc[j][jj] = ffma2(h2v[j].y, w2.y, acc[j][jj]);
                    }
                }
                // smem columns 4..5
                #pragma unroll
                for (int jj = 4; jj < 6; jj++) {
                    ulonglong2 w2 = *(const ulonglong2*)(wbse + jj * WS + s * 4);
                    #pragma unroll
                    for (int j = 0; j < 4; j++) {
                        acc[j][jj] = ffma2(h2v[j].x, w2.x, acc[j][jj]);
                        acc[j][jj] = ffma2(h2v[j].y, w2.y, acc[j][jj]);
                    }
                }
            }
            #pragma unroll
            for (int j = 0; j < 4; j++) {
                int row = rh * 4 + j;
                #pragma unroll
                for (int jj = 0; jj < 6; jj += 2) {
                    float2 p0 = *(float2*)&acc[j][jj];
                    float2 p1 = *(float2*)&acc[j][jj + 1];
                    *(float2*)&red[kc * RKC + row * RB + cg * 6 + jj] =
                        make_float2(p0.x + p0.y, p1.x + p1.y);
                }
            }
        }
        __syncthreads();

        // ---- phase 3: parallel gates with fused k-reduce ----
        if (tid < 128) {
            // layer 1: h1[i]
            if (i < TSTEPS) {
                int b = tid & 7, u = tid >> 3;
                int scol = (sl << 4) + u;
                const float* rrow = red + b * RB;
                float rec[3], xp[3];
                #pragma unroll
                for (int g = 0; g < 3; g++) {
                    int c = g * 16 + u;
                    float s = rrow[c];
                    #pragma unroll
                    for (int k2 = 1; k2 < 8; k2++) s += rrow[k2 * RKC + c];
                    rec[g] = s + sb[48 + c];                 // + b1_rec
                    float a = sb[c];                         // b1_in
                    const float* wr = sW1t + c * 16;
                    const float* xr = sx + b * 16;
                    #pragma unroll
                    for (int f = 0; f < 15; f++) a += xr[f] * wr[f];
                    xp[g] = a;
                }
                float z  = sigmoidf_(xp[0] + rec[0]);
                float r  = sigmoidf_(xp[1] + rec[1]);
                float hh = fmaxf(0.f, xp[2] + r * rec[2]);
                float hn = z * hp1 + (1.f - z) * hh;
                hp1 = hn;
                g_h1[((i & 1) * NGROUPS + grp) * BG * 256 + b * 256 + scol] = hn;
                if (i == TSTEPS - 1) out[64 * 256 + (brow0 + b) * 256 + scol] = hn;  // state1
            }
        } else if (tid < 256) {
            // layer 2: h2[i-1]
            if (i >= 1) {
                int bu = tid - 128;
                int b = bu & 7, u = bu >> 3;
                int scol = (sl << 4) + u;
                int gb = brow0 + b;
                const float* rrow = red + b * RB;
                float xpv[3], rec[3];
                #pragma unroll
                for (int g = 0; g < 3; g++) {
                    int cx = 48 + g * 16 + u;
                    int cr = 96 + g * 16 + u;
                    float sx_ = rrow[cx];
                    float sr_ = rrow[cr];
                    #pragma unroll
                    for (int k2 = 1; k2 < 8; k2++) {
                        sx_ += rrow[k2 * RKC + cx];
                        sr_ += rrow[k2 * RKC + cr];
                    }
                    xpv[g] = sx_ + sb[96 + g * 16 + u];   // + b2_in
                    rec[g] = sr_ + sb[144 + g * 16 + u];  // + b2_rec
                }
                float z  = sigmoidf_(xpv[0] + rec[0]);
                float r  = sigmoidf_(xpv[1] + rec[1]);
                float hh = fmaxf(0.f, xpv[2] + r * rec[2]);
                float hn = z * hp2 + (1.f - z) * hh;
                hp2 = hn;
                g_h2[(((i - 1) & 1) * NGROUPS + grp) * BG * 256 + b * 256 + scol] = hn;
                if (i == TSTEPS) {
                    out[gb * 256 + scol]                = hn;   // x = seq2[:, -1, :]
                    out[2 * 64 * 256 + gb * 256 + scol] = hn;   // state2
                }
            }
        }

        bar_arrive(cta, (unsigned)(i + 2));
    }
}

extern "C" void kernel_launch(void* const* d_in, const int* in_sizes, int n_in,
                              void* d_out, int out_size) {
    const float* inp = (const float*)d_in[0];
    const float* W1  = (const float*)d_in[1];
    const float* U1  = (const float*)d_in[2];
    const float* b1  = (const float*)d_in[3];
    const float* W2  = (const float*)d_in[4];
    const float* U2  = (const float*)d_in[5];
    const float* b2  = (const float*)d_in[6];
    float* out = (float*)d_out;

    size_t smem_bytes = (size_t)(144 * WS + 2 * 8 * SPH +
                                 48 * 16 + 8 * 16 + 4 * 48 +
                                 8 * RKC) * sizeof(float);
    cudaFuncSetAttribute(gru_kernel, cudaFuncAttributeMaxDynamicSharedMemorySize,
                         (int)smem_bytes);
    init_kernel<<<1, 128>>>();
    gru_kernel<<<NCTA, NT, smem_bytes>>>(inp, W1, U1, b1, W2, U2, b2, out);
}

// round 16
// speedup vs baseline: 1.1827x; 1.1786x over previous
#include <cuda_runtime.h>
#include <math.h>

#define TSTEPS  2048
#define FDIM    15
#define NGROUPS 8
#define BG      8      // batch rows per group
#define NT      384
#define NCTA    128
#define SPH     260    // padded row stride for h state (floats), 16B-aligned rows
#define WS      260    // padded row stride for weights (floats), 16B-aligned rows
#define RB      148    // red row stride
#define RKC     1188   // red kc stride = 8*RB + 4

typedef unsigned long long u64;

// Double-buffered hidden states (tiny: live in L2)
__device__ float    g_h1[2 * NGROUPS * BG * 256];
__device__ float    g_h2[2 * NGROUPS * BG * 256];
__device__ unsigned g_flags[NCTA];

__global__ void init_kernel() {
    if (threadIdx.x < NCTA) g_flags[threadIdx.x] = 0u;
}

__device__ __forceinline__ float sigmoidf_(float x) {
    return __fdividef(1.0f, 1.0f + __expf(-x));
}

// packed f32x2 fma
__device__ __forceinline__ u64 ffma2(u64 a, u64 b, u64 c) {
    u64 d;
    asm("fma.rn.f32x2 %0, %1, %2, %3;" : "=l"(d) : "l"(a), "l"(b), "l"(c));
    return d;
}

// arrive: block sync, then tid0 fences + publishes epoch to this CTA's flag
__device__ __forceinline__ void bar_arrive(unsigned cta, unsigned e) {
    __syncthreads();
    if (threadIdx.x == 0) {
        __threadfence();
        atomicExch(&g_flags[cta], e);
    }
}
// wait: warp 0 polls all 16 flags of the group (one 64B sector), broadcast via bar
__device__ __forceinline__ void bar_wait(int grp, unsigned e) {
    if (threadIdx.x < 32) {
        int lane = threadIdx.x;
        for (;;) {
            unsigned v = e;
            if (lane < 16) v = ((volatile unsigned*)g_flags)[grp * 16 + lane];
            if (__all_sync(0xffffffffu, v >= e)) break;
        }
        if (lane == 0) __threadfence();
    }
    __syncthreads();
}

__global__ void __launch_bounds__(NT, 1)
gru_kernel(const float* __restrict__ inp, const float* __restrict__ W1,
           const float* __restrict__ U1g, const float* __restrict__ b1,
           const float* __restrict__ W2g, const float* __restrict__ U2g,
           const float* __restrict__ b2, float* __restrict__ out)
{
    extern __shared__ float smem[];
    float* sW    = smem;                  // [144][WS]: 0..47 U1, 48..95 W2, 96..143 U2 (transposed)
    float* sh1   = sW    + 144 * WS;      // [8][SPH]  h1[i-1]
    float* sh2   = sh1   +   8 * SPH;     // [8][SPH]  h2[i-2]
    float* sW1t  = sh2   +   8 * SPH;     // [48][16]
    float* sx    = sW1t  +  48 * 16;      // [8][16]
    float* sb    = sx    +   8 * 16;      // [4*48]: b1_in | b1_rec | b2_in | b2_rec
    float* red   = sb    +   4 * 48;      // [8 kc][8 rows * RB]

    const int tid   = threadIdx.x;
    const int cta   = blockIdx.x;
    const int grp   = cta >> 4;
    const int sl    = cta & 15;
    const int brow0 = grp * BG;

    // ---- one-time: load weight slices (transposed) into SMEM ----
    for (int idx = tid; idx < 48 * 256; idx += NT) {
        int k = idx / 48, c = idx - k * 48;
        int col = ((c >> 4) << 8) + (sl << 4) + (c & 15);   // gate*256 + slice*16 + u
        sW[c * WS + k]          = U1g[k * 768 + col];
        sW[(48 + c) * WS + k]   = W2g[k * 768 + col];
        sW[(96 + c) * WS + k]   = U2g[k * 768 + col];
    }
    for (int idx = tid; idx < 48 * 15; idx += NT) {
        int f = idx / 48, c = idx - f * 48;
        int col = ((c >> 4) << 8) + (sl << 4) + (c & 15);
        sW1t[c * 16 + f] = W1[f * 768 + col];
    }
    for (int c = tid; c < 48; c += NT) {
        int col = ((c >> 4) << 8) + (sl << 4) + (c & 15);
        sb[c]        = b1[col];        // b1_in
        sb[48 + c]   = b1[768 + col];  // b1_rec
        sb[96 + c]   = b2[col];        // b2_in
        sb[144 + c]  = b2[768 + col];  // b2_rec
    }
    if (tid < 128) {
        int b = tid & 7, u = tid >> 3;
        int scol = (sl << 4) + u;
        for (int buf = 0; buf < 2; buf++) {
            g_h1[(buf * NGROUPS + grp) * BG * 256 + b * 256 + scol] = 0.f;
            g_h2[(buf * NGROUPS + grp) * BG * 256 + b * 256 + scol] = 0.f;
        }
    }
    __syncthreads();

    // GEMM decomposition (all 384 threads): kc (k-chunk of 32) x cg (6 cols) x rh (4 rows)
    const int kc  = tid / 48;          // 0..7
    const int r48 = tid - kc * 48;
    const int cg  = r48 >> 1;          // 0..23 (cols cg*6..cg*6+5; cg<16 -> h1, else h2)
    const int rh  = r48 & 1;           // 0..1
    const float* hsel = (cg < 16 ? sh1 : sh2) + rh * 4 * SPH + kc * 32;
    const float* wbse = sW + (cg * 6) * WS + kc * 32;

    // ---- register-cache weight columns 0..1 of this thread's 6 columns ----
    ulonglong2 wc[2][8];
    #pragma unroll
    for (int jj = 0; jj < 2; jj++)
        #pragma unroll
        for (int s = 0; s < 8; s++)
            wc[jj][s] = *(const ulonglong2*)(wbse + jj * WS + s * 4);

    const int b15 = tid / 15, f15 = tid - b15 * 15;   // input-load map (tid<120)

    // register-resident own state element
    float hp1 = 0.f;   // valid for tid < 128
    float hp2 = 0.f;   // valid for 128 <= tid < 256

    bar_arrive(cta, 1u);
    bar_wait(grp, 1u);

    for (int i = 0; i <= TSTEPS; ++i) {
        // ---- prefetch input row i (independent of barrier) ----
        float xin = 0.f;
        if (i < TSTEPS && tid < 120)
            xin = __ldg(&inp[(size_t)(brow0 + b15) * (TSTEPS * FDIM) + i * FDIM + f15]);

        if (i > 0) bar_wait(grp, (unsigned)(i + 1));

        // ---- phase 1: load shared state (L2-coherent) ----
        {
            const float* gh1 = g_h1 + (((i + 1) & 1) * NGROUPS + grp) * BG * 256;  // h1[i-1]
            const float* gh2 = g_h2 + (((i) & 1)     * NGROUPS + grp) * BG * 256;  // h2[i-2]
            for (int idx = tid; idx < 512; idx += NT) {
                int b = idx >> 6, k4 = idx & 63;
                float4 v1 = __ldcg(((const float4*)(gh1 + b * 256)) + k4);
                float4 v2 = __ldcg(((const float4*)(gh2 + b * 256)) + k4);
                *(float4*)(sh1 + b * SPH + (k4 << 2)) = v1;
                *(float4*)(sh2 + b * SPH + (k4 << 2)) = v2;
            }
            if (i < TSTEPS && tid < 120) sx[b15 * 16 + f15] = xin;
        }
        __syncthreads();

        // ---- phase 2: fused register-tiled GEMM (4x6 tile, 2 w-cols cached in regs) ----
        {
            u64 acc[4][6];
            #pragma unroll
            for (int j = 0; j < 4; j++)
                #pragma unroll
                for (int jj = 0; jj < 6; jj++) acc[j][jj] = 0ull;

            #pragma unroll
            for (int s = 0; s < 8; s++) {
                ulonglong2 h2v[4];
                #pragma unroll
                for (int j = 0; j < 4; j++)
                    h2v[j] = *(const ulonglong2*)(hsel + j * SPH + s * 4);
                // cached columns 0..1
                #pragma unroll
                for (int jj = 0; jj < 2; jj++) {
                    ulonglong2 w2 = wc[jj][s];
                    #pragma unroll
                    for (int j = 0; j < 4; j++) {
                        acc[j][jj] = ffma2(h2v[j].x, w2.x, acc[j][jj]);
                        acc[j][jj] = ffma2(h2v[j].y, w2.y, acc[j][jj]);
                    }
                }
                // smem columns 2..5
                #pragma unroll
                for (int jj = 2; jj < 6; jj++) {
                    ulonglong2 w2 = *(const ulonglong2*)(wbse + jj * WS + s * 4);
                    #pragma unroll
                    for (int j = 0; j < 4; j++) {
                        acc[j][jj] = ffma2(h2v[j].x, w2.x, acc[j][jj]);
                        acc[j][jj] = ffma2(h2v[j].y, w2.y, acc[j][jj]);
                    }
                }
            }
            #pragma unroll
            for (int j = 0; j < 4; j++) {
                int row = rh * 4 + j;
                #pragma unroll
                for (int jj = 0; jj < 6; jj += 2) {
                    float2 p0 = *(float2*)&acc[j][jj];
                    float2 p1 = *(float2*)&acc[j][jj + 1];
                    *(float2*)&red[kc * RKC + row * RB + cg * 6 + jj] =
                        make_float2(p0.x + p0.y, p1.x + p1.y);
                }
            }
        }
        __syncthreads();

        // ---- phase 3: parallel gates with fused k-reduce ----
        if (tid < 128) {
            // layer 1: h1[i]
            if (i < TSTEPS) {
                int b = tid & 7, u = tid >> 3;
                int scol = (sl << 4) + u;
                const float* rrow = red + b * RB;
                float rec[3], xp[3];
                #pragma unroll
                for (int g = 0; g < 3; g++) {
                    int c = g * 16 + u;
                    float s = rrow[c];
                    #pragma unroll
                    for (int k2 = 1; k2 < 8; k2++) s += rrow[k2 * RKC + c];
                    rec[g] = s + sb[48 + c];                 // + b1_rec
                    float a = sb[c];                         // b1_in
                    const float* wr = sW1t + c * 16;
                    const float* xr = sx + b * 16;
                    #pragma unroll
                    for (int f = 0; f < 15; f++) a += xr[f] * wr[f];
                    xp[g] = a;
                }
                float z  = sigmoidf_(xp[0] + rec[0]);
                float r  = sigmoidf_(xp[1] + rec[1]);
                float hh = fmaxf(0.f, xp[2] + r * rec[2]);
                float hn = z * hp1 + (1.f - z) * hh;
                hp1 = hn;
                g_h1[((i & 1) * NGROUPS + grp) * BG * 256 + b * 256 + scol] = hn;
                if (i == TSTEPS - 1) out[64 * 256 + (brow0 + b) * 256 + scol] = hn;  // state1
            }
        } else if (tid < 256) {
            // layer 2: h2[i-1]
            if (i >= 1) {
                int bu = tid - 128;
                int b = bu & 7, u = bu >> 3;
                int scol = (sl << 4) + u;
                int gb = brow0 + b;
                const float* rrow = red + b * RB;
                float xpv[3], rec[3];
                #pragma unroll
                for (int g = 0; g < 3; g++) {
                    int cx = 48 + g * 16 + u;
                    int cr = 96 + g * 16 + u;
                    float sx_ = rrow[cx];
                    float sr_ = rrow[cr];
                    #pragma unroll
                    for (int k2 = 1; k2 < 8; k2++) {
                        sx_ += rrow[k2 * RKC + cx];
                        sr_ += rrow[k2 * RKC + cr];
                    }
                    xpv[g] = sx_ + sb[96 + g * 16 + u];   // + b2_in
                    rec[g] = sr_ + sb[144 + g * 16 + u];  // + b2_rec
                }
                float z  = sigmoidf_(xpv[0] + rec[0]);
                float r  = sigmoidf_(xpv[1] + rec[1]);
                float hh = fmaxf(0.f, xpv[2] + r * rec[2]);
                float hn = z * hp2 + (1.f - z) * hh;
                hp2 = hn;
                g_h2[(((i - 1) & 1) * NGROUPS + grp) * BG * 256 + b * 256 + scol] = hn;
                if (i == TSTEPS) {
                    out[gb * 256 + scol]                = hn;   // x = seq2[:, -1, :]
                    out[2 * 64 * 256 + gb * 256 + scol] = hn;   // state2
                }
            }
        }

        bar_arrive(cta, (unsigned)(i + 2));
    }
}

extern "C" void kernel_launch(void* const* d_in, const int* in_sizes, int n_in,
                              void* d_out, int out_size) {
    const float* inp = (const float*)d_in[0];
    const float* W1  = (const float*)d_in[1];
    const float* U1  = (const float*)d_in[2];
    const float* b1  = (const float*)d_in[3];
    const float* W2  = (const float*)d_in[4];
    const float* U2  = (const float*)d_in[5];
    const float* b2  = (const float*)d_in[6];
    float* out = (float*)d_out;

    size_t smem_bytes = (size_t)(144 * WS + 2 * 8 * SPH +
                                 48 * 16 + 8 * 16 + 4 * 48 +
                                 8 * RKC) * sizeof(float);
    cudaFuncSetAttribute(gru_kernel, cudaFuncAttributeMaxDynamicSharedMemorySize,
                         (int)smem_bytes);
    init_kernel<<<1, 128>>>();
    gru_kernel<<<NCTA, NT, smem_bytes>>>(inp, W1, U1, b1, W2, U2, b2, out);
}